// round 16
// baseline (speedup 1.0000x reference)
#include <cuda_runtime.h>
#include <cuda.h>
#include <cuda_fp16.h>
#include <cstdint>

#define L_SEQ 2048
#define DDIM  2048
#define KTOT  8192
#define BM 128
#define BN 256
#define BK 64
#define NKT (KTOT / BK)        // 128 k-tiles
#define STAGES 4
#define NTHREADS 512

// smem: [0,64): mbarriers (full[s]@s*16, empty[s]@s*16+8); stages at 1024
#define A_BYTES (128 * 128)                  // 16384
#define B_BYTES (256 * 128)                  // 32768
#define STAGE_BYTES (A_BYTES + B_BYTES)      // 49152
#define A_OFF 0
#define B_OFF A_BYTES
#define STAGE0 1024
#define SMEM_TOTAL (STAGE0 + STAGES * STAGE_BYTES)  // 197632 -> 1 CTA/SM

// ---------------- device scratch ----------------
__device__ __align__(128) __half g_x[L_SEQ * DDIM];
__device__ __align__(128) __half g_wt[DDIM * KTOT];   // WT[n][k] K-major, fp16

// ---------------- helpers ----------------
__device__ __forceinline__ uint32_t smem_u32(const void* p) {
    uint32_t a;
    asm("{ .reg .u64 t; cvta.to.shared.u64 t, %1; cvt.u32.u64 %0, t; }" : "=r"(a) : "l"(p));
    return a;
}
#define MBARRIER_INIT(mb, c) \
    asm volatile("mbarrier.init.shared.b64 [%0], %1;" :: "r"(mb), "r"(c) : "memory")
#define MBARRIER_ARRIVE(mb) \
    asm volatile("mbarrier.arrive.shared.b64 _, [%0];" :: "r"(mb) : "memory")
#define MBARRIER_EXPECT_TX(mb, bytes) \
    asm volatile("mbarrier.arrive.expect_tx.shared.b64 _, [%0], %1;" \
                 :: "r"(mb), "r"((uint32_t)(bytes)) : "memory")
#define MBARRIER_WAIT_PARITY(mb, par) do {                                          \
    uint32_t _m = (mb), _p = (par), _done;                                          \
    asm volatile("{\n\t.reg .pred p;\n\t"                                           \
        "mbarrier.try_wait.parity.acquire.cta.shared::cta.b64 p, [%1], %2;\n\t"     \
        "selp.b32 %0, 1, 0, p;\n\t}" : "=r"(_done) : "r"(_m), "r"(_p) : "memory");  \
    if (!_done) {                                                                   \
        asm volatile("{\n\t.reg .pred P1;\n\t"                                      \
        "WL_%=:\n\t"                                                                \
        "mbarrier.try_wait.parity.acquire.cta.shared::cta.b64 P1, [%0], %1, 0x989680;\n\t" \
        "@P1 bra.uni WD_%=;\n\tbra.uni WL_%=;\n\tWD_%=:\n\t}"                       \
        :: "r"(_m), "r"(_p) : "memory");                                            \
    } } while (0)
#define TMA_LOAD_2D(smem_addr, map_ptr, cx, cy, mbar) \
    asm volatile("cp.async.bulk.tensor.2d.shared::cta.global.tile.mbarrier::complete_tx::bytes " \
        "[%0], [%1, {%2, %3}], [%4];" \
        :: "r"((uint32_t)(smem_addr)), "l"(map_ptr), "r"((int)(cx)), "r"((int)(cy)), \
           "r"((uint32_t)(mbar)) : "memory")

__device__ __forceinline__ void ldm_x4(uint32_t* r, uint32_t addr) {
    asm volatile("ldmatrix.sync.aligned.m8n8.x4.shared.b16 {%0,%1,%2,%3}, [%4];"
                 : "=r"(r[0]), "=r"(r[1]), "=r"(r[2]), "=r"(r[3]) : "r"(addr));
}
__device__ __forceinline__ void mma16816(float* c, const uint32_t* a,
                                         uint32_t b0, uint32_t b1) {
    asm volatile(
        "mma.sync.aligned.m16n8k16.row.col.f32.f16.f16.f32 "
        "{%0,%1,%2,%3}, {%4,%5,%6,%7}, {%8,%9}, {%0,%1,%2,%3};"
        : "+f"(c[0]), "+f"(c[1]), "+f"(c[2]), "+f"(c[3])
        : "r"(a[0]), "r"(a[1]), "r"(a[2]), "r"(a[3]), "r"(b0), "r"(b1));
}

// ---------------- fused prep (unchanged) ----------------
#define XBLKS (L_SEQ * DDIM / 4 / 256)         // 4096
#define WBLKS ((KTOT / 64) * (DDIM / 32))      // 8192

__global__ void prep_kernel(const float* __restrict__ x, const float* __restrict__ w) {
    __shared__ float tile[64][33];
    int bid = blockIdx.x;
    if (bid < XBLKS) {
        int i = bid * 256 + threadIdx.x;
        float4 v = reinterpret_cast<const float4*>(x)[i];
        __half2* hp = reinterpret_cast<__half2*>(g_x);
        hp[2 * i]     = __halves2half2(__float2half(v.x), __float2half(v.y));
        hp[2 * i + 1] = __halves2half2(__float2half(v.z), __float2half(v.w));
    } else {
        int wb = bid - XBLKS;
        int nt = (wb & 63) * 32;
        int kt = (wb >> 6) * 64;
        {
            int f = threadIdx.x;
            #pragma unroll
            for (int it = 0; it < 2; it++, f += 256) {
                int kr = f >> 3;
                int nc = (f & 7) * 4;
                float4 v = *reinterpret_cast<const float4*>(
                    w + (size_t)(kt + kr) * DDIM + nt + nc);
                tile[kr][nc + 0] = v.x; tile[kr][nc + 1] = v.y;
                tile[kr][nc + 2] = v.z; tile[kr][nc + 3] = v.w;
            }
        }
        __syncthreads();
        {
            int nrow = threadIdx.x >> 3;
            int kg = (threadIdx.x & 7) * 8;
            __half2 outv[4];
            #pragma unroll
            for (int j = 0; j < 4; j++)
                outv[j] = __halves2half2(__float2half(tile[kg + 2 * j][nrow]),
                                          __float2half(tile[kg + 2 * j + 1][nrow]));
            *reinterpret_cast<float4*>(g_wt + (size_t)(nt + nrow) * KTOT + kt + kg) =
                *reinterpret_cast<float4*>(outv);
        }
    }
}

// ---------------- GEMM: TMA pipeline, 512 threads, 4(M)x4(N) warps ---------
__global__ __launch_bounds__(NTHREADS, 1) void mamba_gemm_mma(
    const __grid_constant__ CUtensorMap a_map,
    const __grid_constant__ CUtensorMap b_map,
    const float* __restrict__ conv_b, const float* __restrict__ D_param,
    float* __restrict__ out)
{
    extern __shared__ __align__(1024) char smem[];
    const uint32_t sbase = smem_u32(smem);
    const uint32_t stage_base = sbase + STAGE0;
    const int tid  = threadIdx.x;
    const int lane = tid & 31;
    const int wid  = tid >> 5;                 // 0..15
    const int wm   = wid & 3;                  // 4 warps along M (32 rows each)
    const int wn   = wid >> 2;                 // 4 warps along N (64 cols each)
    const int bm = blockIdx.y * BM;
    const int bn = blockIdx.x * BN;

    if (tid == 0) {
        #pragma unroll
        for (int s = 0; s < STAGES; s++) {
            MBARRIER_INIT(sbase + s * 16, 1);      // full: expect_tx arrive by tid0
            MBARRIER_INIT(sbase + s * 16 + 8, 16); // empty: one arrive per warp
        }
    }
    __syncthreads();

#define PRODUCE(stage_, ktile_) do {                                           \
    const int w_ = (ktile_) >> 5;                                              \
    const int ibase_ = ((ktile_) & 31) * BK;                                   \
    const uint32_t st_ = stage_base + (stage_) * STAGE_BYTES;                  \
    MBARRIER_EXPECT_TX(sbase + (stage_) * 16, STAGE_BYTES);                    \
    TMA_LOAD_2D(st_ + A_OFF, &a_map, ibase_, bm + w_ - 1, sbase + (stage_) * 16); \
    TMA_LOAD_2D(st_ + B_OFF, &b_map, (ktile_) * BK, bn, sbase + (stage_) * 16);   \
} while (0)

    // prologue: produce stages 0..2
    if (tid == 0) {
        PRODUCE(0, 0);
        PRODUCE(1, 1);
        PRODUCE(2, 2);
    }

    float acc[2][8][4];
    #pragma unroll
    for (int mi = 0; mi < 2; mi++)
        #pragma unroll
        for (int ni = 0; ni < 8; ni++)
            #pragma unroll
            for (int j = 0; j < 4; j++)
                acc[mi][ni][j] = 0.0f;

    const uint32_t a_row   = wm * 32 + (lane & 15);
    const uint32_t a_chunk = (lane >> 4);
    const uint32_t b_row   = wn * 64 + (lane & 7) + ((lane >> 4) << 3);
    const uint32_t b_chunk = ((lane >> 3) & 1);

    int sc = 0, cpar = 0, ccnt = 0;
    int sp = 3, ppar = 0, pcnt = 0;

    for (int kt = 0; kt < NKT; kt++) {
        // ---- produce stage for kt+3 (thread 0 only) ----
        if (kt + 3 < NKT) {
            if (tid == 0) {
                if (kt > 0) MBARRIER_WAIT_PARITY(sbase + sp * 16 + 8, ppar);
                PRODUCE(sp, kt + 3);
            }
            if (kt > 0) { if (++pcnt == STAGES) { pcnt = 0; ppar ^= 1; } }
            if (++sp == STAGES) sp = 0;
        }

        // ---- consume stage sc ----
        MBARRIER_WAIT_PARITY(sbase + sc * 16, cpar);
        const uint32_t st = stage_base + sc * STAGE_BYTES;
        #pragma unroll
        for (int ks = 0; ks < 4; ks++) {
            uint32_t aa[2][4];
            uint32_t bb[4][4];
            #pragma unroll
            for (int mi = 0; mi < 2; mi++) {
                uint32_t row = a_row + mi * 16;
                uint32_t ar = st + A_OFF + row * 128 + (((ks * 2 + a_chunk) ^ (row & 7)) << 4);
                ldm_x4(aa[mi], ar);
            }
            #pragma unroll
            for (int np = 0; np < 4; np++) {
                uint32_t row = b_row + np * 16;
                uint32_t br = st + B_OFF + row * 128 + (((ks * 2 + b_chunk) ^ (row & 7)) << 4);
                ldm_x4(bb[np], br);
            }
            if (ks == 3 && lane == 0)
                MBARRIER_ARRIVE(sbase + sc * 16 + 8);
            #pragma unroll
            for (int mi = 0; mi < 2; mi++)
                #pragma unroll
                for (int ni = 0; ni < 8; ni++) {
                    uint32_t b0 = bb[ni >> 1][(ni & 1) * 2];
                    uint32_t b1 = bb[ni >> 1][(ni & 1) * 2 + 1];
                    mma16816(acc[mi][ni], aa[mi], b0, b1);
                }
        }
        if (++sc == STAGES) sc = 0;
        if (++ccnt == STAGES) { ccnt = 0; cpar ^= 1; }
    }

    // epilogue: (acc + conv_b[n]) * D_param[n]
    #pragma unroll
    for (int ni = 0; ni < 8; ni++) {
        int c = bn + wn * 64 + ni * 8 + (lane & 3) * 2;
        float2 cb = *reinterpret_cast<const float2*>(conv_b + c);
        float2 dp = *reinterpret_cast<const float2*>(D_param + c);
        #pragma unroll
        for (int mi = 0; mi < 2; mi++) {
            int r0 = bm + wm * 32 + mi * 16 + (lane >> 2);
            float2 o0, o1;
            o0.x = (acc[mi][ni][0] + cb.x) * dp.x;
            o0.y = (acc[mi][ni][1] + cb.y) * dp.y;
            o1.x = (acc[mi][ni][2] + cb.x) * dp.x;
            o1.y = (acc[mi][ni][3] + cb.y) * dp.y;
            *reinterpret_cast<float2*>(out + (size_t)r0 * DDIM + c) = o0;
            *reinterpret_cast<float2*>(out + (size_t)(r0 + 8) * DDIM + c) = o1;
        }
    }
}

// ---------------- launch ----------------
typedef CUresult (*EncodeTiledFn)(
    CUtensorMap*, CUtensorMapDataType, cuuint32_t, void*,
    const cuuint64_t*, const cuuint64_t*, const cuuint32_t*, const cuuint32_t*,
    CUtensorMapInterleave, CUtensorMapSwizzle, CUtensorMapL2promotion,
    CUtensorMapFloatOOBfill);

extern "C" void kernel_launch(void* const* d_in, const int* in_sizes, int n_in,
                              void* d_out, int out_size) {
    const float* x       = (const float*)d_in[0];
    const float* conv_k  = (const float*)d_in[3];
    const float* conv_b  = (const float*)d_in[4];
    const float* D_param = (const float*)d_in[6];
    float* out = (float*)d_out;

    prep_kernel<<<XBLKS + WBLKS, 256>>>(x, conv_k);

    void* fn = nullptr;
    cudaDriverEntryPointQueryResult qr;
    cudaGetDriverEntryPoint("cuTensorMapEncodeTiled", &fn, cudaEnableDefault, &qr);
    EncodeTiledFn encode = (EncodeTiledFn)fn;

    void* gx_ptr = nullptr; cudaGetSymbolAddress(&gx_ptr, g_x);
    void* gw_ptr = nullptr; cudaGetSymbolAddress(&gw_ptr, g_wt);

    CUtensorMap a_map, b_map;
    {
        cuuint64_t dims[2]    = {DDIM, L_SEQ};
        cuuint64_t strides[1] = {DDIM * 2};
        cuuint32_t box[2]     = {BK, BM};
        cuuint32_t es[2]      = {1, 1};
        encode(&a_map, CU_TENSOR_MAP_DATA_TYPE_UINT16, 2, gx_ptr,
               dims, strides, box, es,
               CU_TENSOR_MAP_INTERLEAVE_NONE, CU_TENSOR_MAP_SWIZZLE_128B,
               CU_TENSOR_MAP_L2_PROMOTION_L2_128B, CU_TENSOR_MAP_FLOAT_OOB_FILL_NONE);
    }
    {
        cuuint64_t dims[2]    = {KTOT, DDIM};
        cuuint64_t strides[1] = {KTOT * 2};
        cuuint32_t box[2]     = {BK, BN};
        cuuint32_t es[2]      = {1, 1};
        encode(&b_map, CU_TENSOR_MAP_DATA_TYPE_UINT16, 2, gw_ptr,
               dims, strides, box, es,
               CU_TENSOR_MAP_INTERLEAVE_NONE, CU_TENSOR_MAP_SWIZZLE_128B,
               CU_TENSOR_MAP_L2_PROMOTION_L2_128B, CU_TENSOR_MAP_FLOAT_OOB_FILL_NONE);
    }

    cudaFuncSetAttribute(mamba_gemm_mma, cudaFuncAttributeMaxDynamicSharedMemorySize, SMEM_TOTAL);
    mamba_gemm_mma<<<dim3(DDIM / BN, L_SEQ / BM), NTHREADS, SMEM_TOTAL>>>(
        a_map, b_map, conv_b, D_param, out);
}

// round 17
// speedup vs baseline: 1.0667x; 1.0667x over previous
#include <cuda_runtime.h>
#include <cuda.h>
#include <cuda_fp16.h>
#include <cstdint>

#define L_SEQ 2048
#define DDIM  2048
#define KTOT  8192
#define BM 128
#define BN 256
#define BK 64
#define NKT (KTOT / BK)        // 128 k-tiles
#define STAGES 4
#define NTHREADS 256

// smem: [0,64): mbarriers (full[s]@s*16, empty[s]@s*16+8); stages at 1024
#define A_BYTES (128 * 128)                  // 16384
#define B_BYTES (256 * 128)                  // 32768
#define STAGE_BYTES (A_BYTES + B_BYTES)      // 49152
#define A_OFF 0
#define B_OFF A_BYTES
#define STAGE0 1024
#define SMEM_TOTAL (STAGE0 + STAGES * STAGE_BYTES)  // 197632 -> 1 CTA/SM

// ---------------- device scratch ----------------
__device__ __align__(128) __half g_x[L_SEQ * DDIM];
__device__ __align__(128) __half g_wt[DDIM * KTOT];   // WT[n][k] K-major, fp16

// ---------------- helpers ----------------
__device__ __forceinline__ uint32_t smem_u32(const void* p) {
    uint32_t a;
    asm("{ .reg .u64 t; cvta.to.shared.u64 t, %1; cvt.u32.u64 %0, t; }" : "=r"(a) : "l"(p));
    return a;
}
#define MBARRIER_INIT(mb, c) \
    asm volatile("mbarrier.init.shared.b64 [%0], %1;" :: "r"(mb), "r"(c) : "memory")
#define MBARRIER_ARRIVE(mb) \
    asm volatile("mbarrier.arrive.shared.b64 _, [%0];" :: "r"(mb) : "memory")
#define MBARRIER_EXPECT_TX(mb, bytes) \
    asm volatile("mbarrier.arrive.expect_tx.shared.b64 _, [%0], %1;" \
                 :: "r"(mb), "r"((uint32_t)(bytes)) : "memory")
#define MBARRIER_WAIT_PARITY(mb, par) do {                                          \
    uint32_t _m = (mb), _p = (par), _done;                                          \
    asm volatile("{\n\t.reg .pred p;\n\t"                                           \
        "mbarrier.try_wait.parity.acquire.cta.shared::cta.b64 p, [%1], %2;\n\t"     \
        "selp.b32 %0, 1, 0, p;\n\t}" : "=r"(_done) : "r"(_m), "r"(_p) : "memory");  \
    if (!_done) {                                                                   \
        asm volatile("{\n\t.reg .pred P1;\n\t"                                      \
        "WL_%=:\n\t"                                                                \
        "mbarrier.try_wait.parity.acquire.cta.shared::cta.b64 P1, [%0], %1, 0x989680;\n\t" \
        "@P1 bra.uni WD_%=;\n\tbra.uni WL_%=;\n\tWD_%=:\n\t}"                       \
        :: "r"(_m), "r"(_p) : "memory");                                            \
    } } while (0)
#define TMA_LOAD_2D(smem_addr, map_ptr, cx, cy, mbar) \
    asm volatile("cp.async.bulk.tensor.2d.shared::cta.global.tile.mbarrier::complete_tx::bytes " \
        "[%0], [%1, {%2, %3}], [%4];" \
        :: "r"((uint32_t)(smem_addr)), "l"(map_ptr), "r"((int)(cx)), "r"((int)(cy)), \
           "r"((uint32_t)(mbar)) : "memory")

__device__ __forceinline__ void ldm_x4(uint32_t* r, uint32_t addr) {
    asm volatile("ldmatrix.sync.aligned.m8n8.x4.shared.b16 {%0,%1,%2,%3}, [%4];"
                 : "=r"(r[0]), "=r"(r[1]), "=r"(r[2]), "=r"(r[3]) : "r"(addr));
}
__device__ __forceinline__ void mma16816(float* c, const uint32_t* a,
                                         uint32_t b0, uint32_t b1) {
    asm volatile(
        "mma.sync.aligned.m16n8k16.row.col.f32.f16.f16.f32 "
        "{%0,%1,%2,%3}, {%4,%5,%6,%7}, {%8,%9}, {%0,%1,%2,%3};"
        : "+f"(c[0]), "+f"(c[1]), "+f"(c[2]), "+f"(c[3])
        : "r"(a[0]), "r"(a[1]), "r"(a[2]), "r"(a[3]), "r"(b0), "r"(b1));
}

// ---------------- fused prep (unchanged) ----------------
#define XBLKS (L_SEQ * DDIM / 4 / 256)         // 4096
#define WBLKS ((KTOT / 64) * (DDIM / 32))      // 8192

__global__ void prep_kernel(const float* __restrict__ x, const float* __restrict__ w) {
    __shared__ float tile[64][33];
    int bid = blockIdx.x;
    if (bid < XBLKS) {
        int i = bid * 256 + threadIdx.x;
        float4 v = reinterpret_cast<const float4*>(x)[i];
        __half2* hp = reinterpret_cast<__half2*>(g_x);
        hp[2 * i]     = __halves2half2(__float2half(v.x), __float2half(v.y));
        hp[2 * i + 1] = __halves2half2(__float2half(v.z), __float2half(v.w));
    } else {
        int wb = bid - XBLKS;
        int nt = (wb & 63) * 32;
        int kt = (wb >> 6) * 64;
        {
            int f = threadIdx.x;
            #pragma unroll
            for (int it = 0; it < 2; it++, f += 256) {
                int kr = f >> 3;
                int nc = (f & 7) * 4;
                float4 v = *reinterpret_cast<const float4*>(
                    w + (size_t)(kt + kr) * DDIM + nt + nc);
                tile[kr][nc + 0] = v.x; tile[kr][nc + 1] = v.y;
                tile[kr][nc + 2] = v.z; tile[kr][nc + 3] = v.w;
            }
        }
        __syncthreads();
        {
            int nrow = threadIdx.x >> 3;
            int kg = (threadIdx.x & 7) * 8;
            __half2 outv[4];
            #pragma unroll
            for (int j = 0; j < 4; j++)
                outv[j] = __halves2half2(__float2half(tile[kg + 2 * j][nrow]),
                                          __float2half(tile[kg + 2 * j + 1][nrow]));
            *reinterpret_cast<float4*>(g_wt + (size_t)(nt + nrow) * KTOT + kt + kg) =
                *reinterpret_cast<float4*>(outv);
        }
    }
}

// ---------------- GEMM: TMA pipeline, 8 warps 2(M)x4(N), ks-pipelined ------
__global__ __launch_bounds__(NTHREADS, 1) void mamba_gemm_mma(
    const __grid_constant__ CUtensorMap a_map,
    const __grid_constant__ CUtensorMap b_map,
    const float* __restrict__ conv_b, const float* __restrict__ D_param,
    float* __restrict__ out)
{
    extern __shared__ __align__(1024) char smem[];
    const uint32_t sbase = smem_u32(smem);
    const uint32_t stage_base = sbase + STAGE0;
    const int tid  = threadIdx.x;
    const int lane = tid & 31;
    const int wid  = tid >> 5;
    const int wm   = wid & 1;                  // 2 warps along M (64 rows each)
    const int wn   = wid >> 1;                 // 4 warps along N (64 cols each)
    const int bm = blockIdx.y * BM;
    const int bn = blockIdx.x * BN;

    if (tid == 0) {
        #pragma unroll
        for (int s = 0; s < STAGES; s++) {
            MBARRIER_INIT(sbase + s * 16, 1);     // full: expect_tx arrive by tid0
            MBARRIER_INIT(sbase + s * 16 + 8, 8); // empty: one arrive per warp
        }
    }
    __syncthreads();

#define PRODUCE(stage_, ktile_) do {                                           \
    const int w_ = (ktile_) >> 5;                                              \
    const int ibase_ = ((ktile_) & 31) * BK;                                   \
    const uint32_t st_ = stage_base + (stage_) * STAGE_BYTES;                  \
    MBARRIER_EXPECT_TX(sbase + (stage_) * 16, STAGE_BYTES);                    \
    TMA_LOAD_2D(st_ + A_OFF, &a_map, ibase_, bm + w_ - 1, sbase + (stage_) * 16); \
    TMA_LOAD_2D(st_ + B_OFF, &b_map, (ktile_) * BK, bn, sbase + (stage_) * 16);   \
} while (0)

    // prologue: produce stages 0..2
    if (tid == 0) {
        PRODUCE(0, 0);
        PRODUCE(1, 1);
        PRODUCE(2, 2);
    }

    float acc[4][8][4];
    #pragma unroll
    for (int mi = 0; mi < 4; mi++)
        #pragma unroll
        for (int ni = 0; ni < 8; ni++)
            #pragma unroll
            for (int j = 0; j < 4; j++)
                acc[mi][ni][j] = 0.0f;

    const uint32_t a_row   = wm * 64 + (lane & 15);
    const uint32_t a_chunk = (lane >> 4);
    const uint32_t b_row   = wn * 64 + (lane & 7) + ((lane >> 4) << 3);
    const uint32_t b_chunk = ((lane >> 3) & 1);

    // double-buffered fragments (regs: acc 128 + 64 frag + addr ~ 246 < 255)
    uint32_t aa[2][4][4];
    uint32_t bb[2][4][4];

#define LOAD_FRAGS(st_, ks_, buf_) do {                                              \
    _Pragma("unroll")                                                                \
    for (int mi = 0; mi < 4; mi++) {                                                 \
        uint32_t row = a_row + mi * 16;                                              \
        uint32_t ar = (st_) + A_OFF + row * 128 + ((((ks_) * 2 + a_chunk) ^ (row & 7)) << 4); \
        ldm_x4(aa[buf_][mi], ar);                                                    \
    }                                                                                \
    _Pragma("unroll")                                                                \
    for (int np = 0; np < 4; np++) {                                                 \
        uint32_t row = b_row + np * 16;                                              \
        uint32_t br = (st_) + B_OFF + row * 128 + ((((ks_) * 2 + b_chunk) ^ (row & 7)) << 4); \
        ldm_x4(bb[buf_][np], br);                                                    \
    }                                                                                \
} while (0)

    int sc = 0, cpar = 0, ccnt = 0;
    int sp = 3, ppar = 0, pcnt = 0;

    for (int kt = 0; kt < NKT; kt++) {
        // ---- produce stage for kt+3 (thread 0 only) ----
        if (kt + 3 < NKT) {
            if (tid == 0) {
                if (kt > 0) MBARRIER_WAIT_PARITY(sbase + sp * 16 + 8, ppar);
                PRODUCE(sp, kt + 3);
            }
            if (kt > 0) { if (++pcnt == STAGES) { pcnt = 0; ppar ^= 1; } }
            if (++sp == STAGES) sp = 0;
        }

        // ---- consume stage sc (ks-pipelined fragments) ----
        MBARRIER_WAIT_PARITY(sbase + sc * 16, cpar);
        const uint32_t st = stage_base + sc * STAGE_BYTES;
        LOAD_FRAGS(st, 0, 0);
        #pragma unroll
        for (int ks = 0; ks < 4; ks++) {
            const int cur = ks & 1;
            if (ks < 3) LOAD_FRAGS(st, ks + 1, cur ^ 1);
            // all stage reads are issued once ks==3's frags were loaded (at ks==2)
            if (ks == 3 && lane == 0)
                MBARRIER_ARRIVE(sbase + sc * 16 + 8);
            #pragma unroll
            for (int mi = 0; mi < 4; mi++)
                #pragma unroll
                for (int ni = 0; ni < 8; ni++) {
                    uint32_t b0 = bb[cur][ni >> 1][(ni & 1) * 2];
                    uint32_t b1 = bb[cur][ni >> 1][(ni & 1) * 2 + 1];
                    mma16816(acc[mi][ni], aa[cur][mi], b0, b1);
                }
        }
        if (++sc == STAGES) sc = 0;
        if (++ccnt == STAGES) { ccnt = 0; cpar ^= 1; }
    }

    // epilogue: (acc + conv_b[n]) * D_param[n]
    #pragma unroll
    for (int ni = 0; ni < 8; ni++) {
        int c = bn + wn * 64 + ni * 8 + (lane & 3) * 2;
        float2 cb = *reinterpret_cast<const float2*>(conv_b + c);
        float2 dp = *reinterpret_cast<const float2*>(D_param + c);
        #pragma unroll
        for (int mi = 0; mi < 4; mi++) {
            int r0 = bm + wm * 64 + mi * 16 + (lane >> 2);
            float2 o0, o1;
            o0.x = (acc[mi][ni][0] + cb.x) * dp.x;
            o0.y = (acc[mi][ni][1] + cb.y) * dp.y;
            o1.x = (acc[mi][ni][2] + cb.x) * dp.x;
            o1.y = (acc[mi][ni][3] + cb.y) * dp.y;
            *reinterpret_cast<float2*>(out + (size_t)r0 * DDIM + c) = o0;
            *reinterpret_cast<float2*>(out + (size_t)(r0 + 8) * DDIM + c) = o1;
        }
    }
}

// ---------------- launch ----------------
typedef CUresult (*EncodeTiledFn)(
    CUtensorMap*, CUtensorMapDataType, cuuint32_t, void*,
    const cuuint64_t*, const cuuint64_t*, const cuuint32_t*, const cuuint32_t*,
    CUtensorMapInterleave, CUtensorMapSwizzle, CUtensorMapL2promotion,
    CUtensorMapFloatOOBfill);

extern "C" void kernel_launch(void* const* d_in, const int* in_sizes, int n_in,
                              void* d_out, int out_size) {
    const float* x       = (const float*)d_in[0];
    const float* conv_k  = (const float*)d_in[3];
    const float* conv_b  = (const float*)d_in[4];
    const float* D_param = (const float*)d_in[6];
    float* out = (float*)d_out;

    prep_kernel<<<XBLKS + WBLKS, 256>>>(x, conv_k);

    void* fn = nullptr;
    cudaDriverEntryPointQueryResult qr;
    cudaGetDriverEntryPoint("cuTensorMapEncodeTiled", &fn, cudaEnableDefault, &qr);
    EncodeTiledFn encode = (EncodeTiledFn)fn;

    void* gx_ptr = nullptr; cudaGetSymbolAddress(&gx_ptr, g_x);
    void* gw_ptr = nullptr; cudaGetSymbolAddress(&gw_ptr, g_wt);

    CUtensorMap a_map, b_map;
    {
        cuuint64_t dims[2]    = {DDIM, L_SEQ};
        cuuint64_t strides[1] = {DDIM * 2};
        cuuint32_t box[2]     = {BK, BM};
        cuuint32_t es[2]      = {1, 1};
        encode(&a_map, CU_TENSOR_MAP_DATA_TYPE_UINT16, 2, gx_ptr,
               dims, strides, box, es,
               CU_TENSOR_MAP_INTERLEAVE_NONE, CU_TENSOR_MAP_SWIZZLE_128B,
               CU_TENSOR_MAP_L2_PROMOTION_L2_128B, CU_TENSOR_MAP_FLOAT_OOB_FILL_NONE);
    }
    {
        cuuint64_t dims[2]    = {KTOT, DDIM};
        cuuint64_t strides[1] = {KTOT * 2};
        cuuint32_t box[2]     = {BK, BN};
        cuuint32_t es[2]      = {1, 1};
        encode(&b_map, CU_TENSOR_MAP_DATA_TYPE_UINT16, 2, gw_ptr,
               dims, strides, box, es,
               CU_TENSOR_MAP_INTERLEAVE_NONE, CU_TENSOR_MAP_SWIZZLE_128B,
               CU_TENSOR_MAP_L2_PROMOTION_L2_128B, CU_TENSOR_MAP_FLOAT_OOB_FILL_NONE);
    }

    cudaFuncSetAttribute(mamba_gemm_mma, cudaFuncAttributeMaxDynamicSharedMemorySize, SMEM_TOTAL);
    mamba_gemm_mma<<<dim3(DDIM / BN, L_SEQ / BM), NTHREADS, SMEM_TOTAL>>>(
        a_map, b_map, conv_b, D_param, out);
}